// round 10
// baseline (speedup 1.0000x reference)
#include <cuda_runtime.h>
#include <cuda_fp16.h>
#include <math.h>

// ---------------------------------------------------------------------------
// Radon backprojection:
//   K1: build fp16 duplicated-pair chunks: chunk[a][p] = 16B {bin p, bin p+1}
//       (4 batches x fp16 each) + trig table + zero d_out.
//   K2: ONE aligned LDG.128 per (pixel,angle) yields v0 AND v1 for all 4
//       batches; fp32 lerp; 2 pixels/thread; 4-way angle split; RED epilogue.
// ---------------------------------------------------------------------------

#define MAX_A 2048
#define MAX_ELEMS (8 * 1024 * 1024)
#define MAX_CHUNKS (2 * 1024 * 1024)     // A*P chunks, 16 B each (32 MB)
#define PIX_PER_BLK 448
#define NSPLIT 4

__device__ float4 g_trig[MAX_A];          // (cos/dp, sin/dp, (N/2)*sin/dp, 0)
__device__ float  g_c0;                   // -p0/dp
__device__ uint4  g_chunks[MAX_CHUNKS];   // [a][p]: halves {p.b0..b3, (p+1).b0..b3}
__device__ float  g_sino_t[MAX_ELEMS];    // fp32 fallback: [a][p][b]

// K1 (BC==4): fp16 pair-chunk build + trig + zero-init, fused.
__global__ void radon_prep_chunks_kernel(const float* __restrict__ sino,
                                         const float* __restrict__ thetas,
                                         const float* __restrict__ positions,
                                         float4* __restrict__ out4,
                                         int A, int P, int N, int NOUT4)
{
    int idx = blockIdx.x * blockDim.x + threadIdx.x;
    int AP = A * P;

    float p0  = positions[0];
    float dp  = positions[1] - positions[0];
    float inv = 1.0f / dp;

    if (idx < A) {
        float s, c;
        sincosf(thetas[idx], &s, &c);
        float si = s * inv;
        g_trig[idx] = make_float4(c * inv, si, (float)(N >> 1) * si, 0.f);
    }
    if (idx == 0) g_c0 = -p0 * inv;

    if (idx < AP) {
        // 4 batch samples for bin (a,p), converted to fp16 and packed as uint2.
        __half2 h01 = __floats2half2_rn(__ldg(sino + idx),
                                        __ldg(sino + idx + AP));
        __half2 h23 = __floats2half2_rn(__ldg(sino + idx + 2 * AP),
                                        __ldg(sino + idx + 3 * AP));
        uint2 hb;
        hb.x = *(unsigned int*)&h01;
        hb.y = *(unsigned int*)&h23;

        int p = idx % P;
        uint2* chunks2 = (uint2*)g_chunks;         // chunk k = elements [2k,2k+1]
        chunks2[2 * idx] = hb;                     // lo half of chunk p (bin p)
        if (p > 0) chunks2[2 * idx - 1] = hb;      // hi half of chunk p-1 (bin p)
    }
    if (idx < NOUT4)
        out4[idx] = make_float4(0.f, 0.f, 0.f, 0.f);
}

// Generic fp32 prep (fallback path).
__global__ void radon_prep_transpose_kernel(const float* __restrict__ sino,
                                            const float* __restrict__ thetas,
                                            const float* __restrict__ positions,
                                            int BC, int A, int P)
{
    int idx = blockIdx.x * blockDim.x + threadIdx.x;
    int AP = A * P;

    float p0  = positions[0];
    float dp  = positions[1] - positions[0];
    float inv = 1.0f / dp;

    if (idx < A) {
        float s, c;
        sincosf(thetas[idx], &s, &c);
        g_trig[idx] = make_float4(c * inv, s * inv, 0.f, 0.f);
    }
    if (idx == 0) g_c0 = -p0 * inv;

    if (idx < AP) {
        for (int b = 0; b < BC; ++b)
            g_sino_t[idx * BC + b] = __ldg(sino + idx + b * AP);
    }
}

// K2 (BC==4): 2 pixels/thread, 1 LDG.128 per (pixel,angle), fp32 lerp.
__global__ void __launch_bounds__(PIX_PER_BLK, 2)
radon_backproj4_kernel(float* __restrict__ out, int A, int P, int N, int NN)
{
    __shared__ float4 strig[512];
    for (int i = threadIdx.x; i < A; i += blockDim.x) strig[i] = g_trig[i];
    __syncthreads();

    int HALF_NN = NN >> 1;
    int h   = blockIdx.x % NSPLIT;
    int idx = (blockIdx.x / NSPLIT) * PIX_PER_BLK + threadIdx.x;
    if (idx >= HALF_NN) return;

    int x = idx % N;
    int y = idx / N;
    float half = 0.5f * (float)(N - 1);
    float cx = (float)x - half;
    float cy = half - (float)y;
    float c0 = g_c0;
    int   Pm2 = P - 2;

    int chunk = (A + NSPLIT - 1) / NSPLIT;
    int a_lo  = h * chunk;
    int a_hi  = min(A, a_lo + chunk);

    float4 acc1 = make_float4(0.f, 0.f, 0.f, 0.f);
    float4 acc2 = make_float4(0.f, 0.f, 0.f, 0.f);
    const uint4* __restrict__ chunks = g_chunks;

    #pragma unroll 2
    for (int a = a_lo; a < a_hi; ++a) {
        float4 tr = strig[a];
        const uint4* row = chunks + a * P;

        // pixel 1: (x, y)
        float f1  = fmaf(cx, tr.x, fmaf(cy, tr.y, c0));
        float fi1 = floorf(f1);
        int   i1  = min(max((int)fi1, 0), Pm2);
        uint4 q1  = __ldg(row + i1);

        // pixel 2: (x, y + N/2)
        float f2  = f1 - tr.z;
        float fi2 = floorf(f2);
        int   i2  = min(max((int)fi2, 0), Pm2);
        uint4 q2  = __ldg(row + i2);

        float w11 = f1 - fi1, w10 = 1.0f - w11;
        float w21 = f2 - fi2, w20 = 1.0f - w21;

        {
            float2 v0a = __half22float2(*(__half2*)&q1.x);  // bin p: b0,b1
            float2 v0b = __half22float2(*(__half2*)&q1.y);  // bin p: b2,b3
            float2 v1a = __half22float2(*(__half2*)&q1.z);  // bin p+1: b0,b1
            float2 v1b = __half22float2(*(__half2*)&q1.w);  // bin p+1: b2,b3
            acc1.x = fmaf(v0a.x, w10, fmaf(v1a.x, w11, acc1.x));
            acc1.y = fmaf(v0a.y, w10, fmaf(v1a.y, w11, acc1.y));
            acc1.z = fmaf(v0b.x, w10, fmaf(v1b.x, w11, acc1.z));
            acc1.w = fmaf(v0b.y, w10, fmaf(v1b.y, w11, acc1.w));
        }
        {
            float2 v0a = __half22float2(*(__half2*)&q2.x);
            float2 v0b = __half22float2(*(__half2*)&q2.y);
            float2 v1a = __half22float2(*(__half2*)&q2.z);
            float2 v1b = __half22float2(*(__half2*)&q2.w);
            acc2.x = fmaf(v0a.x, w20, fmaf(v1a.x, w21, acc2.x));
            acc2.y = fmaf(v0a.y, w20, fmaf(v1a.y, w21, acc2.y));
            acc2.z = fmaf(v0b.x, w20, fmaf(v1b.x, w21, acc2.z));
            acc2.w = fmaf(v0b.y, w20, fmaf(v1b.y, w21, acc2.w));
        }
    }

    int idx2 = idx + HALF_NN;
    atomicAdd(out + idx,           acc1.x);
    atomicAdd(out + idx + NN,      acc1.y);
    atomicAdd(out + idx + 2 * NN,  acc1.z);
    atomicAdd(out + idx + 3 * NN,  acc1.w);
    atomicAdd(out + idx2,          acc2.x);
    atomicAdd(out + idx2 + NN,     acc2.y);
    atomicAdd(out + idx2 + 2 * NN, acc2.z);
    atomicAdd(out + idx2 + 3 * NN, acc2.w);
}

// Generic fallback (fp32, single pass, validity predicate kept).
__global__ void radon_backproj_generic_kernel(float* __restrict__ out,
                                              int BC, int A, int P, int N, int NN)
{
    __shared__ float2 strig[MAX_A];
    for (int i = threadIdx.x; i < A; i += blockDim.x) {
        float4 t = g_trig[i];
        strig[i] = make_float2(t.x, t.y);
    }
    __syncthreads();

    int idx = blockIdx.x * blockDim.x + threadIdx.x;
    if (idx >= NN) return;

    int x = idx % N;
    int y = idx / N;
    float half = 0.5f * (float)(N - 1);
    float cx = (float)x - half;
    float cy = half - (float)y;
    float c0 = g_c0;
    int   Pm2 = P - 2;

    for (int b = 0; b < BC; ++b) {
        float acc = 0.f;
        for (int a = 0; a < A; ++a) {
            float2 tr = strig[a];
            float f  = fmaf(cx, tr.x, fmaf(cy, tr.y, c0));
            float fi = floorf(f);
            int   i0 = (int)fi;
            bool  valid = (i0 >= 0) && (i0 <= Pm2);
            int   i0c = min(max(i0, 0), Pm2);
            float v0 = g_sino_t[(a * P + i0c) * BC + b];
            float v1 = g_sino_t[(a * P + i0c + 1) * BC + b];
            float w  = f - fi;
            float w1 = valid ? w       : 0.f;
            float w0 = valid ? 1.f - w : 0.f;
            acc = fmaf(v0, w0, fmaf(v1, w1, acc));
        }
        out[b * NN + idx] = acc;
    }
}

extern "C" void kernel_launch(void* const* d_in, const int* in_sizes, int n_in,
                              void* d_out, int out_size)
{
    const float* sino      = (const float*)d_in[0];
    const float* thetas    = (const float*)d_in[1];
    const float* positions = (const float*)d_in[2];

    int A  = in_sizes[1];
    int P  = in_sizes[2];
    int BC = in_sizes[0] / (A * P);
    int N  = (int)(sqrt((double)(out_size / BC)) + 0.5);
    int NN = N * N;
    float* out = (float*)d_out;

    int AP = A * P;
    if (BC == 4 && (N & 1) == 0 && A <= 512 && AP <= MAX_CHUNKS) {
        int NOUT4 = NN;                                  // out has 4*NN floats
        int prep_elems = AP > NOUT4 ? AP : NOUT4;
        radon_prep_chunks_kernel<<<(prep_elems + 255) / 256, 256>>>(
            sino, thetas, positions, (float4*)out, A, P, N, NOUT4);

        int half_nn = NN >> 1;
        int stripes = (half_nn + PIX_PER_BLK - 1) / PIX_PER_BLK;  // 74 for N=256
        radon_backproj4_kernel<<<NSPLIT * stripes, PIX_PER_BLK>>>(out, A, P, N, NN);
    } else {
        radon_prep_transpose_kernel<<<(AP + 255) / 256, 256>>>(sino, thetas, positions, BC, A, P);
        radon_backproj_generic_kernel<<<(NN + 255) / 256, 256>>>(out, BC, A, P, N, NN);
    }
}

// round 11
// speedup vs baseline: 1.7263x; 1.7263x over previous
#include <cuda_runtime.h>
#include <cuda_fp16.h>
#include <math.h>

// ---------------------------------------------------------------------------
// Radon backprojection:
//   K1: fp16 duplicated-pair chunks: chunk[a][p] = 16B {bin p, bin p+1}
//       (4 batches x fp16) + trig table + zero d_out.
//   K2: ONE LDG.128 per (pixel,angle); lerp+accumulate in half2 (full-rate
//       fma pipe), flush to fp32 every 4 angles (cvt amortized 8x);
//       2 pixels/thread; 4-way angle split; RED epilogue.
// ---------------------------------------------------------------------------

#define MAX_A 2048
#define MAX_ELEMS (8 * 1024 * 1024)
#define MAX_CHUNKS (2 * 1024 * 1024)     // A*P chunks, 16 B each
#define PIX_PER_BLK 448
#define NSPLIT 4

__device__ float4 g_trig[MAX_A];          // (cos/dp, sin/dp, (N/2)*sin/dp, 0)
__device__ float  g_c0;                   // -p0/dp
__device__ uint4  g_chunks[MAX_CHUNKS];   // [a][p]: {bin p (4 half), bin p+1 (4 half)}
__device__ float  g_sino_t[MAX_ELEMS];    // fp32 fallback: [a][p][b]

// K1 (BC==4): fp16 pair-chunk build + trig + zero-init, fused.
__global__ void radon_prep_chunks_kernel(const float* __restrict__ sino,
                                         const float* __restrict__ thetas,
                                         const float* __restrict__ positions,
                                         float4* __restrict__ out4,
                                         int A, int P, int N, int NOUT4)
{
    int idx = blockIdx.x * blockDim.x + threadIdx.x;
    int AP = A * P;

    float p0  = positions[0];
    float dp  = positions[1] - positions[0];
    float inv = 1.0f / dp;

    if (idx < A) {
        float s, c;
        sincosf(thetas[idx], &s, &c);
        float si = s * inv;
        g_trig[idx] = make_float4(c * inv, si, (float)(N >> 1) * si, 0.f);
    }
    if (idx == 0) g_c0 = -p0 * inv;

    if (idx < AP) {
        __half2 h01 = __floats2half2_rn(__ldg(sino + idx),
                                        __ldg(sino + idx + AP));
        __half2 h23 = __floats2half2_rn(__ldg(sino + idx + 2 * AP),
                                        __ldg(sino + idx + 3 * AP));
        uint2 hb;
        hb.x = *(unsigned int*)&h01;
        hb.y = *(unsigned int*)&h23;

        int p = idx % P;
        uint2* chunks2 = (uint2*)g_chunks;         // chunk k = uint2 pair [2k,2k+1]
        chunks2[2 * idx] = hb;                     // lo half of chunk p (bin p)
        if (p > 0) chunks2[2 * idx - 1] = hb;      // hi half of chunk p-1 (bin p)
    }
    if (idx < NOUT4)
        out4[idx] = make_float4(0.f, 0.f, 0.f, 0.f);
}

// Generic fp32 prep (fallback path).
__global__ void radon_prep_transpose_kernel(const float* __restrict__ sino,
                                            const float* __restrict__ thetas,
                                            const float* __restrict__ positions,
                                            int BC, int A, int P)
{
    int idx = blockIdx.x * blockDim.x + threadIdx.x;
    int AP = A * P;

    float p0  = positions[0];
    float dp  = positions[1] - positions[0];
    float inv = 1.0f / dp;

    if (idx < A) {
        float s, c;
        sincosf(thetas[idx], &s, &c);
        g_trig[idx] = make_float4(c * inv, s * inv, 0.f, 0.f);
    }
    if (idx == 0) g_c0 = -p0 * inv;

    if (idx < AP) {
        for (int b = 0; b < BC; ++b)
            g_sino_t[idx * BC + b] = __ldg(sino + idx + b * AP);
    }
}

// K2 (BC==4): 2 pixels/thread, half2 lerp+acc, fp32 flush every 4 angles.
__global__ void __launch_bounds__(PIX_PER_BLK, 2)
radon_backproj4_kernel(float* __restrict__ out, int A, int P, int N, int NN)
{
    __shared__ float4 strig[512];
    for (int i = threadIdx.x; i < A; i += blockDim.x) strig[i] = g_trig[i];
    __syncthreads();

    int HALF_NN = NN >> 1;
    int h   = blockIdx.x % NSPLIT;
    int idx = (blockIdx.x / NSPLIT) * PIX_PER_BLK + threadIdx.x;
    if (idx >= HALF_NN) return;

    int x = idx % N;
    int y = idx / N;
    float half = 0.5f * (float)(N - 1);
    float cx = (float)x - half;
    float cy = half - (float)y;
    float c0 = g_c0;
    int   Pm2 = P - 2;

    int chunk = (A + NSPLIT - 1) / NSPLIT;
    int a_lo  = h * chunk;
    int a_hi  = min(A, a_lo + chunk);

    float4 acc1 = make_float4(0.f, 0.f, 0.f, 0.f);
    float4 acc2 = make_float4(0.f, 0.f, 0.f, 0.f);
    const uint4* __restrict__ chunks = g_chunks;
    const __half2 hz = __float2half2_rn(0.f);

    int a = a_lo;
    // Main loop: groups of 4 angles, half2 accumulation, fp32 flush per group.
    for (; a + 4 <= a_hi; a += 4) {
        __half2 hA1 = hz, hB1 = hz, hA2 = hz, hB2 = hz;
        #pragma unroll
        for (int k = 0; k < 4; ++k) {
            float4 tr = strig[a + k];
            const uint4* row = chunks + (a + k) * P;

            float f1  = fmaf(cx, tr.x, fmaf(cy, tr.y, c0));
            float fi1 = floorf(f1);
            int   i1  = min(max((int)fi1, 0), Pm2);
            uint4 q1  = __ldg(row + i1);

            float f2  = f1 - tr.z;
            float fi2 = floorf(f2);
            int   i2  = min(max((int)fi2, 0), Pm2);
            uint4 q2  = __ldg(row + i2);

            __half2 w1h = __float2half2_rn(f1 - fi1);
            __half2 w2h = __float2half2_rn(f2 - fi2);

            __half2 v0a1 = *(__half2*)&q1.x, v0b1 = *(__half2*)&q1.y;
            __half2 v1a1 = *(__half2*)&q1.z, v1b1 = *(__half2*)&q1.w;
            hA1 = __hfma2(__hsub2(v1a1, v0a1), w1h, __hadd2(hA1, v0a1));
            hB1 = __hfma2(__hsub2(v1b1, v0b1), w1h, __hadd2(hB1, v0b1));

            __half2 v0a2 = *(__half2*)&q2.x, v0b2 = *(__half2*)&q2.y;
            __half2 v1a2 = *(__half2*)&q2.z, v1b2 = *(__half2*)&q2.w;
            hA2 = __hfma2(__hsub2(v1a2, v0a2), w2h, __hadd2(hA2, v0a2));
            hB2 = __hfma2(__hsub2(v1b2, v0b2), w2h, __hadd2(hB2, v0b2));
        }
        float2 fA1 = __half22float2(hA1), fB1 = __half22float2(hB1);
        float2 fA2 = __half22float2(hA2), fB2 = __half22float2(hB2);
        acc1.x += fA1.x; acc1.y += fA1.y; acc1.z += fB1.x; acc1.w += fB1.y;
        acc2.x += fA2.x; acc2.y += fA2.y; acc2.z += fB2.x; acc2.w += fB2.y;
    }
    // Tail: remaining angles, fp32 lerp.
    for (; a < a_hi; ++a) {
        float4 tr = strig[a];
        const uint4* row = chunks + a * P;

        float f1  = fmaf(cx, tr.x, fmaf(cy, tr.y, c0));
        float fi1 = floorf(f1);
        int   i1  = min(max((int)fi1, 0), Pm2);
        uint4 q1  = __ldg(row + i1);

        float f2  = f1 - tr.z;
        float fi2 = floorf(f2);
        int   i2  = min(max((int)fi2, 0), Pm2);
        uint4 q2  = __ldg(row + i2);

        float w11 = f1 - fi1, w10 = 1.0f - w11;
        float w21 = f2 - fi2, w20 = 1.0f - w21;

        float2 v0a = __half22float2(*(__half2*)&q1.x);
        float2 v0b = __half22float2(*(__half2*)&q1.y);
        float2 v1a = __half22float2(*(__half2*)&q1.z);
        float2 v1b = __half22float2(*(__half2*)&q1.w);
        acc1.x = fmaf(v0a.x, w10, fmaf(v1a.x, w11, acc1.x));
        acc1.y = fmaf(v0a.y, w10, fmaf(v1a.y, w11, acc1.y));
        acc1.z = fmaf(v0b.x, w10, fmaf(v1b.x, w11, acc1.z));
        acc1.w = fmaf(v0b.y, w10, fmaf(v1b.y, w11, acc1.w));

        v0a = __half22float2(*(__half2*)&q2.x);
        v0b = __half22float2(*(__half2*)&q2.y);
        v1a = __half22float2(*(__half2*)&q2.z);
        v1b = __half22float2(*(__half2*)&q2.w);
        acc2.x = fmaf(v0a.x, w20, fmaf(v1a.x, w21, acc2.x));
        acc2.y = fmaf(v0a.y, w20, fmaf(v1a.y, w21, acc2.y));
        acc2.z = fmaf(v0b.x, w20, fmaf(v1b.x, w21, acc2.z));
        acc2.w = fmaf(v0b.y, w20, fmaf(v1b.y, w21, acc2.w));
    }

    int idx2 = idx + HALF_NN;
    atomicAdd(out + idx,           acc1.x);
    atomicAdd(out + idx + NN,      acc1.y);
    atomicAdd(out + idx + 2 * NN,  acc1.z);
    atomicAdd(out + idx + 3 * NN,  acc1.w);
    atomicAdd(out + idx2,          acc2.x);
    atomicAdd(out + idx2 + NN,     acc2.y);
    atomicAdd(out + idx2 + 2 * NN, acc2.z);
    atomicAdd(out + idx2 + 3 * NN, acc2.w);
}

// Generic fallback (fp32, single pass, validity predicate kept).
__global__ void radon_backproj_generic_kernel(float* __restrict__ out,
                                              int BC, int A, int P, int N, int NN)
{
    __shared__ float2 strig[MAX_A];
    for (int i = threadIdx.x; i < A; i += blockDim.x) {
        float4 t = g_trig[i];
        strig[i] = make_float2(t.x, t.y);
    }
    __syncthreads();

    int idx = blockIdx.x * blockDim.x + threadIdx.x;
    if (idx >= NN) return;

    int x = idx % N;
    int y = idx / N;
    float half = 0.5f * (float)(N - 1);
    float cx = (float)x - half;
    float cy = half - (float)y;
    float c0 = g_c0;
    int   Pm2 = P - 2;

    for (int b = 0; b < BC; ++b) {
        float acc = 0.f;
        for (int a = 0; a < A; ++a) {
            float2 tr = strig[a];
            float f  = fmaf(cx, tr.x, fmaf(cy, tr.y, c0));
            float fi = floorf(f);
            int   i0 = (int)fi;
            bool  valid = (i0 >= 0) && (i0 <= Pm2);
            int   i0c = min(max(i0, 0), Pm2);
            float v0 = g_sino_t[(a * P + i0c) * BC + b];
            float v1 = g_sino_t[(a * P + i0c + 1) * BC + b];
            float w  = f - fi;
            float w1 = valid ? w       : 0.f;
            float w0 = valid ? 1.f - w : 0.f;
            acc = fmaf(v0, w0, fmaf(v1, w1, acc));
        }
        out[b * NN + idx] = acc;
    }
}

extern "C" void kernel_launch(void* const* d_in, const int* in_sizes, int n_in,
                              void* d_out, int out_size)
{
    const float* sino      = (const float*)d_in[0];
    const float* thetas    = (const float*)d_in[1];
    const float* positions = (const float*)d_in[2];

    int A  = in_sizes[1];
    int P  = in_sizes[2];
    int BC = in_sizes[0] / (A * P);
    int N  = (int)(sqrt((double)(out_size / BC)) + 0.5);
    int NN = N * N;
    float* out = (float*)d_out;

    int AP = A * P;
    if (BC == 4 && (N & 1) == 0 && A <= 512 && AP <= MAX_CHUNKS) {
        int NOUT4 = NN;                                  // out has 4*NN floats
        int prep_elems = AP > NOUT4 ? AP : NOUT4;
        radon_prep_chunks_kernel<<<(prep_elems + 255) / 256, 256>>>(
            sino, thetas, positions, (float4*)out, A, P, N, NOUT4);

        int half_nn = NN >> 1;
        int stripes = (half_nn + PIX_PER_BLK - 1) / PIX_PER_BLK;  // 74 for N=256
        radon_backproj4_kernel<<<NSPLIT * stripes, PIX_PER_BLK>>>(out, A, P, N, NN);
    } else {
        radon_prep_transpose_kernel<<<(AP + 255) / 256, 256>>>(sino, thetas, positions, BC, A, P);
        radon_backproj_generic_kernel<<<(NN + 255) / 256, 256>>>(out, BC, A, P, N, NN);
    }
}